// round 3
// baseline (speedup 1.0000x reference)
#include <cuda_runtime.h>
#include <math.h>

#define BB 2
#define TT 4096
#define DD 768
#define HH 12
#define DHD 64
#define MTOT (BB*TT)        // 8192
#define NQKV (3*DD)         // 2304

// Scratch (static device allocations are allowed; cudaMalloc is not).
__device__ float g_q[(size_t)BB*HH*TT*DHD];     // [b*H+h][t][d]
__device__ float g_k[(size_t)BB*HH*TT*DHD];
__device__ float g_v[(size_t)BB*HH*TT*DHD];
__device__ float g_attn[(size_t)MTOT*DD];       // [b*T+t][h*64+d]

// ---------------------------------------------------------------------------
// QKV GEMM: qkv = x @ W_qkv + b_qkv, scattered into g_q/g_k/g_v.
// 64x64 tile, BK=16, 256 threads, 4x4 microtile, reg-double-buffered staging.
// ---------------------------------------------------------------------------
__global__ void __launch_bounds__(256) qkv_gemm_kernel(
    const float* __restrict__ x, const float* __restrict__ W,
    const float* __restrict__ bias)
{
    __shared__ float As[16][68];   // [kk][m] (transposed store)
    __shared__ float Bs[16][68];   // [kk][n]
    const int tid = threadIdx.x;
    const int tx = tid & 15, ty = tid >> 4;
    const int n0 = blockIdx.x * 64;
    const int m0 = blockIdx.y * 64;
    const int ar = tid >> 2, ac4 = tid & 3;     // A loader: 64 rows x 4 float4
    const int br = tid >> 4, bc4 = tid & 15;    // B loader: 16 rows x 16 float4

    float acc[4][4] = {};
    // Prefetch first k-tile into registers.
    float4 av = *(const float4*)&x[(size_t)(m0 + ar) * DD + ac4 * 4];
    float4 bv = *(const float4*)&W[(size_t)br * NQKV + n0 + bc4 * 4];

    for (int k0 = 0; k0 < DD; k0 += 16) {
        __syncthreads();
        As[ac4*4+0][ar] = av.x; As[ac4*4+1][ar] = av.y;
        As[ac4*4+2][ar] = av.z; As[ac4*4+3][ar] = av.w;
        *(float4*)&Bs[br][bc4*4] = bv;
        __syncthreads();
        if (k0 + 16 < DD) {   // prefetch next tile; latency hidden under FMAs
            av = *(const float4*)&x[(size_t)(m0 + ar) * DD + (k0+16) + ac4 * 4];
            bv = *(const float4*)&W[(size_t)(k0+16 + br) * NQKV + n0 + bc4 * 4];
        }
        #pragma unroll
        for (int kk = 0; kk < 16; kk++) {
            float4 af = *(const float4*)&As[kk][ty*4];
            float4 bf = *(const float4*)&Bs[kk][tx*4];
            float a[4] = {af.x, af.y, af.z, af.w};
            float b[4] = {bf.x, bf.y, bf.z, bf.w};
            #pragma unroll
            for (int i = 0; i < 4; i++)
                #pragma unroll
                for (int j = 0; j < 4; j++)
                    acc[i][j] += a[i] * b[j];
        }
    }
    // Epilogue: add bias, scatter to q/k/v in [b*H+h][t][d] layout.
    #pragma unroll
    for (int i = 0; i < 4; i++) {
        int m = m0 + ty*4 + i;
        int b_ = m / TT, t = m - b_ * TT;
        #pragma unroll
        for (int j = 0; j < 4; j++) {
            int n = n0 + tx*4 + j;
            float v = acc[i][j] + bias[n];
            int which = n / DD;
            int rem = n - which * DD;
            int h = rem >> 6;
            int d = rem & 63;
            size_t idx = ((size_t)(b_*HH + h) * TT + t) * DHD + d;
            if (which == 0)      g_q[idx] = v;
            else if (which == 1) g_k[idx] = v;
            else                 g_v[idx] = v;
        }
    }
}

// ---------------------------------------------------------------------------
// Flash attention, causal, fp32. One CTA = 64 queries of one (b,h).
// SMEM: Qs/Ks d-major transposed [d][row] (bcast+contig reads),
//       Vs row-major [k][d], Ps row-major [qrow][k] (bcast reads in PV).
// K/V staging is register double-buffered across k-tiles.
// ---------------------------------------------------------------------------
#define ATTN_SMEM (4 * 64 * 68 * 4)

__global__ void __launch_bounds__(256) attn_kernel()
{
    extern __shared__ float sm[];
    float (*Qs)[68] = (float(*)[68])(sm);
    float (*Ks)[68] = (float(*)[68])(sm + 64*68);
    float (*Vs)[68] = (float(*)[68])(sm + 2*64*68);
    float (*Ps)[68] = (float(*)[68])(sm + 3*64*68);

    const int tid = threadIdx.x;
    const int tx = tid & 15, ty = tid >> 4;
    const int qt = (gridDim.x - 1) - blockIdx.x;   // heavy tiles first
    const int bh = blockIdx.y;
    const float* Qg = g_q + (size_t)bh * TT * DHD;
    const float* Kg = g_k + (size_t)bh * TT * DHD;
    const float* Vg = g_v + (size_t)bh * TT * DHD;
    const float scale = 0.125f;  // 1/sqrt(64)

    const int lr  = tid >> 4;        // loader row base (0..15), +16 per step
    const int lc4 = tid & 15;        // loader col (float4 index)

    // Load Q tile, pre-scaled, transposed to [d][row].
    #pragma unroll
    for (int l = 0; l < 4; l++) {
        int r = lr + l * 16;
        float4 v = *(const float4*)&Qg[(size_t)(qt*64 + r) * DHD + lc4*4];
        Qs[lc4*4+0][r] = v.x * scale; Qs[lc4*4+1][r] = v.y * scale;
        Qs[lc4*4+2][r] = v.z * scale; Qs[lc4*4+3][r] = v.w * scale;
    }

    float m_i[4] = {-INFINITY, -INFINITY, -INFINITY, -INFINITY};
    float l_i[4] = {};
    float o[4][4] = {};

    // Prefetch kt=0 K/V into registers.
    float4 kreg[4], vreg[4];
    #pragma unroll
    for (int l = 0; l < 4; l++) {
        int r = lr + l * 16;
        kreg[l] = *(const float4*)&Kg[(size_t)r * DHD + lc4*4];
        vreg[l] = *(const float4*)&Vg[(size_t)r * DHD + lc4*4];
    }

    for (int kt = 0; kt <= qt; kt++) {
        __syncthreads();   // previous PV done reading Vs/Ps
        #pragma unroll
        for (int l = 0; l < 4; l++) {
            int r = lr + l * 16;
            Ks[lc4*4+0][r] = kreg[l].x; Ks[lc4*4+1][r] = kreg[l].y;
            Ks[lc4*4+2][r] = kreg[l].z; Ks[lc4*4+3][r] = kreg[l].w;
            *(float4*)&Vs[r][lc4*4] = vreg[l];
        }
        __syncthreads();
        if (kt < qt) {     // prefetch next tile; latency hidden under S compute
            #pragma unroll
            for (int l = 0; l < 4; l++) {
                int r = lr + l * 16;
                kreg[l] = *(const float4*)&Kg[(size_t)((kt+1)*64 + r) * DHD + lc4*4];
                vreg[l] = *(const float4*)&Vg[(size_t)((kt+1)*64 + r) * DHD + lc4*4];
            }
        }

        // S = (Q*scale) K^T  (4x4 per thread)
        float s[4][4] = {};
        #pragma unroll 8
        for (int d = 0; d < 64; d++) {
            float4 qf = *(const float4*)&Qs[d][ty*4];
            float4 kf = *(const float4*)&Ks[d][tx*4];
            float a[4] = {qf.x, qf.y, qf.z, qf.w};
            float b[4] = {kf.x, kf.y, kf.z, kf.w};
            #pragma unroll
            for (int i = 0; i < 4; i++)
                #pragma unroll
                for (int j = 0; j < 4; j++)
                    s[i][j] += a[i] * b[j];
        }
        if (kt == qt) {   // diagonal tile: causal mask
            #pragma unroll
            for (int i = 0; i < 4; i++)
                #pragma unroll
                for (int j = 0; j < 4; j++)
                    if (tx*4 + j > ty*4 + i) s[i][j] = -1e30f;
        }

        // Online softmax: row max/sum via 16-lane shuffle groups.
        #pragma unroll
        for (int i = 0; i < 4; i++) {
            float rmax = fmaxf(fmaxf(s[i][0], s[i][1]), fmaxf(s[i][2], s[i][3]));
            #pragma unroll
            for (int msk = 1; msk < 16; msk <<= 1)
                rmax = fmaxf(rmax, __shfl_xor_sync(0xffffffffu, rmax, msk));
            float mnew = fmaxf(m_i[i], rmax);
            float alpha = __expf(m_i[i] - mnew);
            m_i[i] = mnew;
            float rsum = 0.f;
            #pragma unroll
            for (int j = 0; j < 4; j++) {
                float p = __expf(s[i][j] - mnew);
                s[i][j] = p;
                rsum += p;
            }
            #pragma unroll
            for (int msk = 1; msk < 16; msk <<= 1)
                rsum += __shfl_xor_sync(0xffffffffu, rsum, msk);
            l_i[i] = l_i[i] * alpha + rsum;
            #pragma unroll
            for (int j = 0; j < 4; j++) o[i][j] *= alpha;
            #pragma unroll
            for (int j = 0; j < 4; j++) Ps[ty*4 + i][tx*4 + j] = s[i][j];
        }
        __syncthreads();

        // O += P @ V
        #pragma unroll 4
        for (int k = 0; k < 64; k++) {
            float4 vf = *(const float4*)&Vs[k][tx*4];
            float vb[4] = {vf.x, vf.y, vf.z, vf.w};
            float pa[4];
            #pragma unroll
            for (int i = 0; i < 4; i++) pa[i] = Ps[ty*4 + i][k];
            #pragma unroll
            for (int i = 0; i < 4; i++)
                #pragma unroll
                for (int j = 0; j < 4; j++)
                    o[i][j] += pa[i] * vb[j];
        }
    }

    // Finalize and write to [b*T+t][h*64+d].
    const int b_ = bh / HH, h = bh % HH;
    #pragma unroll
    for (int i = 0; i < 4; i++) {
        float inv = 1.0f / l_i[i];
        int t = qt*64 + ty*4 + i;
        float4 w = make_float4(o[i][0]*inv, o[i][1]*inv, o[i][2]*inv, o[i][3]*inv);
        *(float4*)&g_attn[((size_t)(b_*TT + t)) * DD + h*DHD + tx*4] = w;
    }
}

// ---------------------------------------------------------------------------
// Output projection: out = attn @ W_out + b_out   (8192 x 768 x 768)
// ---------------------------------------------------------------------------
__global__ void __launch_bounds__(256) out_gemm_kernel(
    const float* __restrict__ W, const float* __restrict__ bias,
    float* __restrict__ out)
{
    __shared__ float As[16][68];
    __shared__ float Bs[16][68];
    const int tid = threadIdx.x;
    const int tx = tid & 15, ty = tid >> 4;
    const int n0 = blockIdx.x * 64;
    const int m0 = blockIdx.y * 64;
    const int ar = tid >> 2, ac4 = tid & 3;
    const int br = tid >> 4, bc4 = tid & 15;

    float acc[4][4] = {};
    float4 av = *(const float4*)&g_attn[(size_t)(m0 + ar) * DD + ac4 * 4];
    float4 bv = *(const float4*)&W[(size_t)br * DD + n0 + bc4 * 4];

    for (int k0 = 0; k0 < DD; k0 += 16) {
        __syncthreads();
        As[ac4*4+0][ar] = av.x; As[ac4*4+1][ar] = av.y;
        As[ac4*4+2][ar] = av.z; As[ac4*4+3][ar] = av.w;
        *(float4*)&Bs[br][bc4*4] = bv;
        __syncthreads();
        if (k0 + 16 < DD) {
            av = *(const float4*)&g_attn[(size_t)(m0 + ar) * DD + (k0+16) + ac4 * 4];
            bv = *(const float4*)&W[(size_t)(k0+16 + br) * DD + n0 + bc4 * 4];
        }
        #pragma unroll
        for (int kk = 0; kk < 16; kk++) {
            float4 af = *(const float4*)&As[kk][ty*4];
            float4 bf = *(const float4*)&Bs[kk][tx*4];
            float a[4] = {af.x, af.y, af.z, af.w};
            float b[4] = {bf.x, bf.y, bf.z, bf.w};
            #pragma unroll
            for (int i = 0; i < 4; i++)
                #pragma unroll
                for (int j = 0; j < 4; j++)
                    acc[i][j] += a[i] * b[j];
        }
    }
    #pragma unroll
    for (int i = 0; i < 4; i++) {
        int m = m0 + ty*4 + i;
        int n = n0 + tx*4;
        float4 w = make_float4(acc[i][0] + bias[n+0], acc[i][1] + bias[n+1],
                               acc[i][2] + bias[n+2], acc[i][3] + bias[n+3]);
        *(float4*)&out[(size_t)m * DD + n] = w;
    }
}

// ---------------------------------------------------------------------------
extern "C" void kernel_launch(void* const* d_in, const int* in_sizes, int n_in,
                              void* d_out, int out_size)
{
    const float* x     = (const float*)d_in[0];
    const float* W_qkv = (const float*)d_in[1];
    const float* b_qkv = (const float*)d_in[2];
    const float* W_out = (const float*)d_in[3];
    const float* b_out = (const float*)d_in[4];
    float* out = (float*)d_out;

    (void)in_sizes; (void)n_in; (void)out_size;

    cudaFuncSetAttribute(attn_kernel,
                         cudaFuncAttributeMaxDynamicSharedMemorySize, ATTN_SMEM);

    qkv_gemm_kernel<<<dim3(NQKV/64, MTOT/64), 256>>>(x, W_qkv, b_qkv);
    attn_kernel<<<dim3(TT/64, BB*HH), 256, ATTN_SMEM>>>();
    out_gemm_kernel<<<dim3(DD/64, MTOT/64), 256>>>(W_out, b_out, out);
}

// round 4
// speedup vs baseline: 2.8002x; 2.8002x over previous
#include <cuda_runtime.h>
#include <cstdint>
#include <math.h>

#define BB 2
#define TT 4096
#define DD 768
#define HH 12
#define DHD 64
#define MTOT (BB*TT)
#define NQKV (3*DD)
#define KD2 (DD/2)   // 384 pair-columns

// bf16 hi/lo split scratch. Pair-packed u32 (even k low half), pairs permuted
// within blocks of 8: slot(j)=((j&3)<<1)|(j>>2) so frag pairs {t,t+4} adjacent.
__device__ uint32_t g_xh [(size_t)MTOT*KD2], g_xl [(size_t)MTOT*KD2];
__device__ uint32_t g_wqh[(size_t)NQKV*KD2], g_wql[(size_t)NQKV*KD2];
__device__ uint32_t g_woh[(size_t)DD*KD2],   g_wol[(size_t)DD*KD2];
__device__ uint32_t g_qh [(size_t)BB*HH*TT*32], g_ql [(size_t)BB*HH*TT*32];
__device__ uint32_t g_kh [(size_t)BB*HH*TT*32], g_kl [(size_t)BB*HH*TT*32];
__device__ uint32_t g_vh [(size_t)BB*HH*DHD*(TT/2)], g_vl[(size_t)BB*HH*DHD*(TT/2)];
__device__ uint32_t g_oh [(size_t)MTOT*KD2], g_ol [(size_t)MTOT*KD2];

__device__ __forceinline__ uint32_t slot8(uint32_t j){ return ((j&3u)<<1)|(j>>2); }

__device__ __forceinline__ void split2(float e, float o, uint32_t &hi, uint32_t &lo){
    uint32_t eh = __float_as_uint(e) & 0xffff0000u;
    uint32_t oh = __float_as_uint(o) & 0xffff0000u;
    float el = e - __uint_as_float(eh);
    float ol = o - __uint_as_float(oh);
    hi = (eh >> 16) | oh;
    lo = ((__float_as_uint(el) & 0xffff0000u) >> 16) | (__float_as_uint(ol) & 0xffff0000u);
}
__device__ __forceinline__ void mma16816(float* c, const uint32_t* a, const uint32_t* b){
    asm volatile("mma.sync.aligned.m16n8k16.row.col.f32.bf16.bf16.f32 "
        "{%0,%1,%2,%3}, {%4,%5,%6,%7}, {%8,%9}, {%0,%1,%2,%3};\n"
        : "+f"(c[0]), "+f"(c[1]), "+f"(c[2]), "+f"(c[3])
        : "r"(a[0]), "r"(a[1]), "r"(a[2]), "r"(a[3]), "r"(b[0]), "r"(b[1]));
}
__device__ __forceinline__ void cp16(uint32_t dst, const void* src){
    asm volatile("cp.async.cg.shared.global [%0], [%1], 16;\n" :: "r"(dst), "l"(src) : "memory");
}
#define CP_COMMIT() asm volatile("cp.async.commit_group;\n" ::: "memory")
#define CP_WAIT1()  asm volatile("cp.async.wait_group 1;\n" ::: "memory")
#define CP_WAIT0()  asm volatile("cp.async.wait_group 0;\n" ::: "memory")
__device__ __forceinline__ float ex2(float x){ float y; asm("ex2.approx.f32 %0,%1;":"=f"(y):"f"(x)); return y; }

// ---- prep: split x rows ----
__global__ void __launch_bounds__(256) split_rows_kernel(
    const float* __restrict__ src, uint32_t* __restrict__ dh, uint32_t* __restrict__ dl, int total)
{
    int idx = blockIdx.x*256 + threadIdx.x;
    if (idx >= total) return;
    int m = idx / KD2, J = idx - m*KD2;
    float2 v = *(const float2*)(src + (size_t)m*DD + 2*J);
    uint32_t hi, lo; split2(v.x, v.y, hi, lo);
    int col = (J & ~7) | slot8(J & 7);
    dh[(size_t)m*KD2 + col] = hi;
    dl[(size_t)m*KD2 + col] = lo;
}
// ---- prep: transpose+split W[K][N] -> [n][KD2] ----
__global__ void __launch_bounds__(256) splitT_w_kernel(
    const float* __restrict__ W, uint32_t* __restrict__ dh, uint32_t* __restrict__ dl, int N)
{
    int idx = blockIdx.x*256 + threadIdx.x;
    if (idx >= N*KD2) return;
    int J = idx / N, n = idx - J*N;
    float a = W[(size_t)(2*J)*N + n];
    float b = W[(size_t)(2*J+1)*N + n];
    uint32_t hi, lo; split2(a, b, hi, lo);
    int col = (J & ~7) | slot8(J & 7);
    dh[(size_t)n*KD2 + col] = hi;
    dl[(size_t)n*KD2 + col] = lo;
}

// ---- GEMM core: C[128x128] = A*B^T, 8 warps, cp.async 2-stage, K=768 ----
__device__ __forceinline__ void gemm_tile(
    const uint32_t* __restrict__ Ah, const uint32_t* __restrict__ Al,
    const uint32_t* __restrict__ Bh, const uint32_t* __restrict__ Bl,
    int m0, int n0, uint32_t* sm, float c[2][8][4])
{
    const int tid = threadIdx.x, lane = tid & 31, wid = tid >> 5;
    const int g = lane >> 2, t = lane & 3;
    const int wm = (wid & 3) * 32, wn = (wid >> 2) * 64;
    const int frow = tid >> 1, fc4 = (tid & 1) * 4;
    uint32_t sb = (uint32_t)__cvta_generic_to_shared(sm);
    {
        uint32_t d = sb + (uint32_t)(frow*8 + fc4)*4u;
        cp16(d,       Ah + (size_t)(m0+frow)*KD2 + fc4);
        cp16(d+4096,  Al + (size_t)(m0+frow)*KD2 + fc4);
        cp16(d+8192,  Bh + (size_t)(n0+frow)*KD2 + fc4);
        cp16(d+12288, Bl + (size_t)(n0+frow)*KD2 + fc4);
        CP_COMMIT();
    }
    for (int kb = 0; kb < 48; kb++){
        int s = kb & 1;
        if (kb < 47){
            uint32_t d = sb + (uint32_t)((s^1)*16384) + (uint32_t)(frow*8 + fc4)*4u;
            size_t off = (size_t)(kb+1)*8 + fc4;
            cp16(d,       Ah + (size_t)(m0+frow)*KD2 + off);
            cp16(d+4096,  Al + (size_t)(m0+frow)*KD2 + off);
            cp16(d+8192,  Bh + (size_t)(n0+frow)*KD2 + off);
            cp16(d+12288, Bl + (size_t)(n0+frow)*KD2 + off);
            CP_COMMIT(); CP_WAIT1();
        } else CP_WAIT0();
        __syncthreads();
        const uint32_t* sAh = sm + s*4096;
        const uint32_t* sAl = sAh + 1024;
        const uint32_t* sBh = sAh + 2048;
        const uint32_t* sBl = sAh + 3072;
        uint32_t aH[2][4], aL[2][4];
        #pragma unroll
        for (int mt = 0; mt < 2; mt++){
            int r0 = wm + mt*16 + g;
            uint2 u0 = *(const uint2*)(sAh + r0*8 + t*2);
            uint2 u1 = *(const uint2*)(sAh + (r0+8)*8 + t*2);
            aH[mt][0]=u0.x; aH[mt][1]=u1.x; aH[mt][2]=u0.y; aH[mt][3]=u1.y;
            uint2 v0 = *(const uint2*)(sAl + r0*8 + t*2);
            uint2 v1 = *(const uint2*)(sAl + (r0+8)*8 + t*2);
            aL[mt][0]=v0.x; aL[mt][1]=v1.x; aL[mt][2]=v0.y; aL[mt][3]=v1.y;
        }
        #pragma unroll
        for (int nt = 0; nt < 8; nt++){
            int rb = wn + nt*8 + g;
            uint2 b0 = *(const uint2*)(sBh + rb*8 + t*2);
            uint2 b1 = *(const uint2*)(sBl + rb*8 + t*2);
            uint32_t bH[2] = {b0.x, b0.y}, bL[2] = {b1.x, b1.y};
            #pragma unroll
            for (int mt = 0; mt < 2; mt++){
                mma16816(c[mt][nt], aH[mt], bH);
                mma16816(c[mt][nt], aH[mt], bL);
                mma16816(c[mt][nt], aL[mt], bH);
            }
        }
        __syncthreads();
    }
}

// ---- QKV GEMM + scatter ----
__global__ void __launch_bounds__(256) qkv_mma_kernel(const float* __restrict__ bias)
{
    __shared__ uint32_t sm[8192];
    float c[2][8][4] = {};
    const int n0 = blockIdx.x * 128, m0 = blockIdx.y * 128;
    gemm_tile(g_xh, g_xl, g_wqh, g_wql, m0, n0, sm, c);

    const int tid = threadIdx.x, lane = tid & 31, wid = tid >> 5;
    const int g = lane >> 2, t = lane & 3;
    const int wm = (wid & 3) * 32, wn = (wid >> 2) * 64;
    const int which = n0 / DD;
    #pragma unroll
    for (int mt = 0; mt < 2; mt++)
    #pragma unroll
    for (int nt = 0; nt < 8; nt++){
        int nbase = n0 + wn + nt*8 + 2*t;
        float2 bi = *(const float2*)(bias + nbase);
        int nloc = nbase - which*DD;
        int h = nloc >> 6, d = nloc & 63;
        #pragma unroll
        for (int rh = 0; rh < 2; rh++){
            int m = m0 + wm + mt*16 + g + rh*8;
            float v0 = c[mt][nt][rh*2+0] + bi.x;
            float v1 = c[mt][nt][rh*2+1] + bi.y;
            int b_ = m >> 12, tk = m & 4095;
            int bh = b_*HH + h;
            if (which < 2){
                uint32_t hi, lo; split2(v0, v1, hi, lo);
                int J = d >> 1;
                int col = (J & ~7) | slot8(J & 7);
                size_t idx = ((size_t)bh*TT + tk)*32 + col;
                if (which == 0){ g_qh[idx] = hi; g_ql[idx] = lo; }
                else           { g_kh[idx] = hi; g_kl[idx] = lo; }
            } else {
                int Jt = tk >> 1;
                int colt = (Jt & ~7) | slot8(Jt & 7);
                size_t i0 = (((size_t)bh*DHD + d  )*2048 + colt)*2 + (tk & 1);
                size_t i1 = (((size_t)bh*DHD + d+1)*2048 + colt)*2 + (tk & 1);
                uint32_t u0 = __float_as_uint(v0), u1 = __float_as_uint(v1);
                float r0 = v0 - __uint_as_float(u0 & 0xffff0000u);
                float r1 = v1 - __uint_as_float(u1 & 0xffff0000u);
                ((uint16_t*)g_vh)[i0] = (uint16_t)(u0 >> 16);
                ((uint16_t*)g_vh)[i1] = (uint16_t)(u1 >> 16);
                ((uint16_t*)g_vl)[i0] = (uint16_t)(__float_as_uint(r0) >> 16);
                ((uint16_t*)g_vl)[i1] = (uint16_t)(__float_as_uint(r1) >> 16);
            }
        }
    }
}

// ---- attention ----
#define ATTN_SMEM_BYTES (20480*4)
__device__ __forceinline__ void attn_fill_kv(uint32_t sb, int s, int kt, int tid, int bh){
    #pragma unroll
    for (int i = 0; i < 4; i++){
        int L = tid + i*128;
        int r = L >> 3, c4 = L & 7;
        int pcol = ((2*c4) ^ ((r & 3) << 2)) * 2;
        uint32_t db = sb + (uint32_t)(4096 + s*8192 + r*32 + pcol)*4u;
        cp16(db,          g_kh + ((size_t)bh*TT + kt*64 + r)*32 + c4*4);
        cp16(db + 8192,   g_kl + ((size_t)bh*TT + kt*64 + r)*32 + c4*4);
        cp16(db + 16384,  g_vh + ((size_t)bh*DHD + r)*2048 + kt*32 + c4*4);
        cp16(db + 24576,  g_vl + ((size_t)bh*DHD + r)*2048 + kt*32 + c4*4);
    }
    CP_COMMIT();
}

__global__ void __launch_bounds__(128) attn_mma_kernel()
{
    extern __shared__ uint32_t sm[];
    const int tid = threadIdx.x, lane = tid & 31, w = tid >> 5;
    const int g = lane >> 2, t = lane & 3;
    const int qt = (int)(gridDim.x - 1 - blockIdx.x);
    const int bh = blockIdx.y;
    uint32_t sb = (uint32_t)__cvta_generic_to_shared(sm);

    attn_fill_kv(sb, 0, 0, tid, bh);

    #pragma unroll
    for (int i = 0; i < 4; i++){
        int L = tid + i*128;
        int r = L >> 3, c4 = L & 7;
        int pcol = ((2*c4) ^ ((r & 3) << 2)) * 2;
        uint4 vh4 = *(const uint4*)(g_qh + ((size_t)bh*TT + qt*64 + r)*32 + c4*4);
        uint4 vl4 = *(const uint4*)(g_ql + ((size_t)bh*TT + qt*64 + r)*32 + c4*4);
        *(uint4*)(sm + r*32 + pcol) = vh4;
        *(uint4*)(sm + 2048 + r*32 + pcol) = vl4;
    }
    __syncthreads();

    uint32_t qfh[4][4], qfl[4][4];
    #pragma unroll
    for (int kc = 0; kc < 4; kc++){
        int phys = ((kc*4 + t) ^ ((g & 3) << 2)) * 2;
        int r0 = w*16 + g;
        uint2 u0 = *(const uint2*)(sm + r0*32 + phys);
        uint2 u1 = *(const uint2*)(sm + (r0+8)*32 + phys);
        qfh[kc][0]=u0.x; qfh[kc][1]=u1.x; qfh[kc][2]=u0.y; qfh[kc][3]=u1.y;
        uint2 v0 = *(const uint2*)(sm + 2048 + r0*32 + phys);
        uint2 v1 = *(const uint2*)(sm + 2048 + (r0+8)*32 + phys);
        qfl[kc][0]=v0.x; qfl[kc][1]=v1.x; qfl[kc][2]=v0.y; qfl[kc][3]=v1.y;
    }

    const float SC = 0.18033688011112042f;   // 0.125 * log2(e)
    float m0r = -INFINITY, m1r = -INFINITY, l0 = 0.f, l1 = 0.f;
    float o[8][4] = {};

    for (int kt = 0; kt <= qt; kt++){
        int s = kt & 1;
        if (kt < qt){ attn_fill_kv(sb, s^1, kt+1, tid, bh); CP_WAIT1(); }
        else CP_WAIT0();
        __syncthreads();
        const uint32_t* kh_s = sm + 4096 + s*8192;
        const uint32_t* kl_s = kh_s + 2048;
        const uint32_t* vh_s = kh_s + 4096;
        const uint32_t* vl_s = kh_s + 6144;

        float cs[8][4] = {};
        #pragma unroll
        for (int kc = 0; kc < 4; kc++){
            int phys = ((kc*4 + t) ^ ((g & 3) << 2)) * 2;
            #pragma unroll
            for (int nt = 0; nt < 8; nt++){
                int rr = nt*8 + g;
                uint2 b0 = *(const uint2*)(kh_s + rr*32 + phys);
                uint2 b1 = *(const uint2*)(kl_s + rr*32 + phys);
                uint32_t bH[2] = {b0.x, b0.y}, bL[2] = {b1.x, b1.y};
                mma16816(cs[nt], qfh[kc], bH);
                mma16816(cs[nt], qfh[kc], bL);
                mma16816(cs[nt], qfl[kc], bH);
            }
        }
        if (kt == qt){
            #pragma unroll
            for (int nt = 0; nt < 8; nt++)
            #pragma unroll
            for (int e = 0; e < 4; e++){
                int col = nt*8 + 2*t + (e & 1);
                int row = w*16 + g + ((e >> 1) << 3);
                cs[nt][e] = (col <= row) ? cs[nt][e]*SC : -1e30f;
            }
        } else {
            #pragma unroll
            for (int nt = 0; nt < 8; nt++)
            #pragma unroll
            for (int e = 0; e < 4; e++) cs[nt][e] *= SC;
        }

        float rmax0 = -1e30f, rmax1 = -1e30f;
        #pragma unroll
        for (int nt = 0; nt < 8; nt++){
            rmax0 = fmaxf(rmax0, fmaxf(cs[nt][0], cs[nt][1]));
            rmax1 = fmaxf(rmax1, fmaxf(cs[nt][2], cs[nt][3]));
        }
        rmax0 = fmaxf(rmax0, __shfl_xor_sync(~0u, rmax0, 1));
        rmax0 = fmaxf(rmax0, __shfl_xor_sync(~0u, rmax0, 2));
        rmax1 = fmaxf(rmax1, __shfl_xor_sync(~0u, rmax1, 1));
        rmax1 = fmaxf(rmax1, __shfl_xor_sync(~0u, rmax1, 2));
        float mn0 = fmaxf(m0r, rmax0), mn1 = fmaxf(m1r, rmax1);
        float al0 = ex2(m0r - mn0), al1 = ex2(m1r - mn1);
        m0r = mn0; m1r = mn1;
        float rs0 = 0.f, rs1 = 0.f;
        #pragma unroll
        for (int nt = 0; nt < 8; nt++){
            cs[nt][0] = ex2(cs[nt][0] - mn0);
            cs[nt][1] = ex2(cs[nt][1] - mn0);
            cs[nt][2] = ex2(cs[nt][2] - mn1);
            cs[nt][3] = ex2(cs[nt][3] - mn1);
            rs0 += cs[nt][0] + cs[nt][1];
            rs1 += cs[nt][2] + cs[nt][3];
        }
        rs0 += __shfl_xor_sync(~0u, rs0, 1);
        rs0 += __shfl_xor_sync(~0u, rs0, 2);
        rs1 += __shfl_xor_sync(~0u, rs1, 1);
        rs1 += __shfl_xor_sync(~0u, rs1, 2);
        l0 = l0*al0 + rs0;
        l1 = l1*al1 + rs1;
        #pragma unroll
        for (int dt = 0; dt < 8; dt++){
            o[dt][0] *= al0; o[dt][1] *= al0;
            o[dt][2] *= al1; o[dt][3] *= al1;
        }
        #pragma unroll
        for (int kc = 0; kc < 4; kc++){
            uint32_t pH[4], pL[4];
            split2(cs[2*kc  ][0], cs[2*kc  ][1], pH[0], pL[0]);
            split2(cs[2*kc  ][2], cs[2*kc  ][3], pH[1], pL[1]);
            split2(cs[2*kc+1][0], cs[2*kc+1][1], pH[2], pL[2]);
            split2(cs[2*kc+1][2], cs[2*kc+1][3], pH[3], pL[3]);
            int phys = ((kc*4 + t) ^ ((g & 3) << 2)) * 2;
            #pragma unroll
            for (int dt = 0; dt < 8; dt++){
                int rr = dt*8 + g;
                uint2 b0 = *(const uint2*)(vh_s + rr*32 + phys);
                uint2 b1 = *(const uint2*)(vl_s + rr*32 + phys);
                uint32_t bH[2] = {b0.x, b0.y}, bL[2] = {b1.x, b1.y};
                mma16816(o[dt], pH, bH);
                mma16816(o[dt], pH, bL);
                mma16816(o[dt], pL, bH);
            }
        }
        __syncthreads();
    }

    float i0 = 1.f / l0, i1 = 1.f / l1;
    int b_ = bh / HH, h = bh - b_*HH;
    int tq0 = qt*64 + w*16 + g;
    size_t mr0 = (size_t)(b_*TT + tq0) * KD2;
    size_t mr1 = (size_t)(b_*TT + tq0 + 8) * KD2;
    #pragma unroll
    for (int dt = 0; dt < 8; dt++){
        int Jg = h*32 + dt*4 + t;
        int col = (Jg & ~7) | slot8(Jg & 7);
        uint32_t hi, lo;
        split2(o[dt][0]*i0, o[dt][1]*i0, hi, lo);
        g_oh[mr0 + col] = hi; g_ol[mr0 + col] = lo;
        split2(o[dt][2]*i1, o[dt][3]*i1, hi, lo);
        g_oh[mr1 + col] = hi; g_ol[mr1 + col] = lo;
    }
}

// ---- output projection ----
__global__ void __launch_bounds__(256) out_mma_kernel(
    const float* __restrict__ bias, float* __restrict__ out)
{
    __shared__ uint32_t sm[8192];
    float c[2][8][4] = {};
    const int n0 = blockIdx.x * 128, m0 = blockIdx.y * 128;
    gemm_tile(g_oh, g_ol, g_woh, g_wol, m0, n0, sm, c);

    const int tid = threadIdx.x, lane = tid & 31, wid = tid >> 5;
    const int g = lane >> 2, t = lane & 3;
    const int wm = (wid & 3) * 32, wn = (wid >> 2) * 64;
    #pragma unroll
    for (int mt = 0; mt < 2; mt++)
    #pragma unroll
    for (int nt = 0; nt < 8; nt++){
        int nb = n0 + wn + nt*8 + 2*t;
        float2 bi = *(const float2*)(bias + nb);
        #pragma unroll
        for (int rh = 0; rh < 2; rh++){
            int m = m0 + wm + mt*16 + g + rh*8;
            *(float2*)&out[(size_t)m*DD + nb] =
                make_float2(c[mt][nt][rh*2+0] + bi.x, c[mt][nt][rh*2+1] + bi.y);
        }
    }
}

// ---------------------------------------------------------------------------
extern "C" void kernel_launch(void* const* d_in, const int* in_sizes, int n_in,
                              void* d_out, int out_size)
{
    const float* x     = (const float*)d_in[0];
    const float* W_qkv = (const float*)d_in[1];
    const float* b_qkv = (const float*)d_in[2];
    const float* W_out = (const float*)d_in[3];
    const float* b_out = (const float*)d_in[4];
    float* out = (float*)d_out;
    (void)in_sizes; (void)n_in; (void)out_size;

    cudaFuncSetAttribute(attn_mma_kernel,
                         cudaFuncAttributeMaxDynamicSharedMemorySize, ATTN_SMEM_BYTES);

    uint32_t *xh, *xl, *wqh, *wql, *woh, *wol;
    cudaGetSymbolAddress((void**)&xh,  g_xh);  cudaGetSymbolAddress((void**)&xl,  g_xl);
    cudaGetSymbolAddress((void**)&wqh, g_wqh); cudaGetSymbolAddress((void**)&wql, g_wql);
    cudaGetSymbolAddress((void**)&woh, g_woh); cudaGetSymbolAddress((void**)&wol, g_wol);

    int txs = MTOT*KD2;
    split_rows_kernel<<<(txs+255)/256, 256>>>(x, xh, xl, txs);
    int twq = NQKV*KD2;
    splitT_w_kernel<<<(twq+255)/256, 256>>>(W_qkv, wqh, wql, NQKV);
    int two = DD*KD2;
    splitT_w_kernel<<<(two+255)/256, 256>>>(W_out, woh, wol, DD);

    qkv_mma_kernel<<<dim3(NQKV/128, MTOT/128), 256>>>(b_qkv);
    attn_mma_kernel<<<dim3(TT/64, BB*HH), 128, ATTN_SMEM_BYTES>>>();
    out_mma_kernel<<<dim3(DD/128, MTOT/128), 256>>>(b_out, out);
}